// round 10
// baseline (speedup 1.0000x reference)
#include <cuda_runtime.h>
#include <stdint.h>
#include <math.h>

#define POINCARE_BOUND 0.99999f
typedef unsigned long long u64;

// ---------------------------------------------------------------------------
// all weights + biases in constant memory (LDC port, 8-cyc floor, imm addr)
// ---------------------------------------------------------------------------
__constant__ __align__(16) float cWc1[32 * 64];
__constant__ __align__(16) float cWc2[32 * 64];
__constant__ __align__(16) float cW0 [64 * 64];
__constant__ __align__(16) float cW1 [64 * 32];
__constant__ __align__(16) float cbc [64];
__constant__ __align__(16) float cb0 [64];
__constant__ __align__(16) float cb1 [32];

// ---------------------------------------------------------------------------
// packed f32x2 primitives
// ---------------------------------------------------------------------------
__device__ __forceinline__ u64 pk2(float lo, float hi) {
    u64 r; asm("mov.b64 %0, {%1, %2};" : "=l"(r) : "f"(lo), "f"(hi)); return r;
}
__device__ __forceinline__ void upk2(u64 v, float& lo, float& hi) {
    asm("mov.b64 {%0, %1}, %2;" : "=f"(lo), "=f"(hi) : "l"(v));
}
__device__ __forceinline__ u64 fma2(u64 a, u64 b, u64 c) {
    u64 d; asm("fma.rn.f32x2 %0, %1, %2, %3;" : "=l"(d) : "l"(a), "l"(b), "l"(c)); return d;
}
__device__ __forceinline__ u64 mul2(u64 a, u64 b) {
    u64 d; asm("mul.rn.f32x2 %0, %1, %2;" : "=l"(d) : "l"(a), "l"(b)); return d;
}
__device__ __forceinline__ float hsum2(u64 v) {
    float lo, hi; upk2(v, lo, hi); return lo + hi;
}

// ---------------------------------------------------------------------------
// fast scalar math
// ---------------------------------------------------------------------------
__device__ __forceinline__ float rcpf(float x)  { float r; asm("rcp.approx.f32 %0, %1;"  : "=f"(r) : "f"(x)); return r; }
__device__ __forceinline__ float sqrtfa(float x){ float r; asm("sqrt.approx.f32 %0, %1;" : "=f"(r) : "f"(x)); return r; }
__device__ __forceinline__ float lg2fa(float x) { float r; asm("lg2.approx.f32 %0, %1;"  : "=f"(r) : "f"(x)); return r; }
__device__ __forceinline__ float ex2fa(float x) { float r; asm("ex2.approx.f32 %0, %1;"  : "=f"(r) : "f"(x)); return r; }

__device__ __forceinline__ float log_scale(float ss) {    // atanh(min(n,B))/n
    float n = fmaxf(sqrtfa(ss), 1e-15f);
    float m = fminf(n, POINCARE_BOUND);
    float r = (1.f + m) * rcpf(1.f - m);
    return (0.34657359f * lg2fa(r)) * rcpf(n);
}
__device__ __forceinline__ float exp_scale(float ss) {     // tanh(n)/n
    float n = fmaxf(sqrtfa(ss), 1e-15f);
    float e = ex2fa(n * -2.8853901f);
    return ((1.f - e) * rcpf(1.f + e)) * rcpf(n);
}
__device__ __forceinline__ void mobius_coef(float x2, float y2, float xy, float& a, float& b) {
    float inv = rcpf(fmaxf(1.f + 2.f * xy + x2 * y2, 1e-15f));
    a = (1.f + 2.f * xy + y2) * inv;
    b = (1.f - x2) * inv;
}

// concat scalar chain (round-7 math): coefficients for v = fa*raw1+fb*raw2+fc*bc
__device__ __forceinline__ void concat_coefs(float ss1, float ss2, float d12,
                                             float d1c, float d2c, float bc2,
                                             float& fa, float& fb, float& fc) {
    float s1 = exp_scale(ss1), s2 = exp_scale(ss2);
    float a, b; mobius_coef(s1*s1*ss1, s2*s2*ss2, s1*s2*d12, a, b);
    float p = a * s1, q = b * s2;
    float m2  = p*p*ss1 + q*q*ss2 + 2.f*p*q*d12;
    float mbc = p*d1c + q*d2c;
    float a2, b2; mobius_coef(m2, bc2, mbc, a2, b2);
    float al = a2 * p, be = a2 * q, gc = b2;
    float g2 = al*al*ss1 + be*be*ss2 + gc*gc*bc2
             + 2.f*(al*be*d12 + al*gc*d1c + be*gc*d2c);
    float sL = log_scale(g2);
    fa = sL * al; fb = sL * be; fc = sL * gc;
}
// layer scalar chain: v = fg*raw + fd*bias  (with final logmap)
__device__ __forceinline__ void layer_coefs(float ss, float d, float bsq,
                                            float& fg, float& fd) {
    float s = exp_scale(ss);
    float a, b; mobius_coef(s*s*ss, bsq, s*d, a, b);
    float ga = a * s, de = b;
    float g2 = ga*ga*ss + de*de*bsq + 2.f*ga*de*d;
    float sL = log_scale(g2);
    fg = sL * ga; fd = sL * de;
}
// last layer (no logmap): out = pa*raw + pb*bias
__device__ __forceinline__ void out_coefs(float ss, float d, float bsq,
                                          float& pa, float& pb) {
    float s = exp_scale(ss);
    float a, b; mobius_coef(s*s*ss, bsq, s*d, a, b);
    pa = a * s; pb = b;
}

// load 32-wide row, pack, apply logmap0
__device__ __forceinline__ void load_log32p(const float* __restrict__ gx, int row, u64* v2) {
    const float4* xp = reinterpret_cast<const float4*>(gx + (size_t)row * 32);
    u64 a = 0ull;
#pragma unroll
    for (int i = 0; i < 8; ++i) {
        float4 v = xp[i];
        u64 p0 = pk2(v.x, v.y), p1 = pk2(v.z, v.w);
        v2[2 * i] = p0; v2[2 * i + 1] = p1;
        a = fma2(p0, p0, a);
        a = fma2(p1, p1, a);
    }
    float s = log_scale(hsum2(a));
    const u64 s2 = pk2(s, s);
#pragma unroll
    for (int i = 0; i < 16; ++i) v2[i] = mul2(v2[i], s2);
}

// ---------------------------------------------------------------------------
// kernel: 128 threads, 2 rows each (t and t+128 of a 256-row block).
// rowA vectors in registers; rowB raw vectors in private smem columns.
// smem buffers (u64 slots, stride 128): P=[0,32) Q=[32,64) R=[64,96)
// ---------------------------------------------------------------------------
__global__ void __launch_bounds__(128, 2)
poincare_mlp_kernel(const float* __restrict__ gx1,
                    const float* __restrict__ gx2,
                    float* __restrict__ gout,
                    int N)
{
    extern __shared__ u64 smraw[];
    const int tid = threadIdx.x;
    u64* P = smraw + tid;              // raw1A  -> later raw3B
    u64* Q = smraw + 32 * 128 + tid;   // raw1B  -> later vB (layer-0 input)
    u64* R = smraw + 64 * 128 + tid;   // raw2B  -> later raw4B

    int rA = blockIdx.x * 256 + tid;
    int rB = rA + 128;
    rA = rA < N ? rA : N - 1;
    rB = rB < N ? rB : N - 1;

    // bias self-dots (packed; warp-uniform LDC)
    float bc2, b0sq, b1sq;
    {
        const u64* b = reinterpret_cast<const u64*>(cbc);
        u64 a = 0ull;
#pragma unroll
        for (int i = 0; i < 32; ++i) a = fma2(b[i], b[i], a);
        bc2 = hsum2(a);
        b = reinterpret_cast<const u64*>(cb0); a = 0ull;
#pragma unroll
        for (int i = 0; i < 32; ++i) a = fma2(b[i], b[i], a);
        b0sq = hsum2(a);
        b = reinterpret_cast<const u64*>(cb1); a = 0ull;
#pragma unroll
        for (int i = 0; i < 16; ++i) a = fma2(b[i], b[i], a);
        b1sq = hsum2(a);
    }

    // ======== branch 1: raw1 = logmap0(x1) @ Wc1 -> P (rowA), Q (rowB) ======
    float ss1A, ss1B, d1cA, d1cB;
    {
        u64 uA[16], uB[16];
        load_log32p(gx1, rA, uA);
        load_log32p(gx1, rB, uB);
        u64 sA = 0, sB = 0, eA = 0, eB = 0;
#pragma unroll
        for (int c0 = 0; c0 < 64; c0 += 16) {
            u64 aA[8], aB[8];
#pragma unroll
            for (int j = 0; j < 8; ++j) { aA[j] = 0; aB[j] = 0; }
#pragma unroll
            for (int k2 = 0; k2 < 16; ++k2) {
                float lo, hi;
                upk2(uA[k2], lo, hi); const u64 va0 = pk2(lo, lo), va1 = pk2(hi, hi);
                upk2(uB[k2], lo, hi); const u64 vb0 = pk2(lo, lo), vb1 = pk2(hi, hi);
                const ulonglong2* w0 = reinterpret_cast<const ulonglong2*>(cWc1 + (2*k2)*64 + c0);
                const ulonglong2* w1 = reinterpret_cast<const ulonglong2*>(cWc1 + (2*k2+1)*64 + c0);
#pragma unroll
                for (int j = 0; j < 4; ++j) {
                    ulonglong2 wa = w0[j], wb = w1[j];
                    aA[2*j]   = fma2(va0, wa.x, aA[2*j]);   aA[2*j+1] = fma2(va0, wa.y, aA[2*j+1]);
                    aA[2*j]   = fma2(va1, wb.x, aA[2*j]);   aA[2*j+1] = fma2(va1, wb.y, aA[2*j+1]);
                    aB[2*j]   = fma2(vb0, wa.x, aB[2*j]);   aB[2*j+1] = fma2(vb0, wa.y, aB[2*j+1]);
                    aB[2*j]   = fma2(vb1, wb.x, aB[2*j]);   aB[2*j+1] = fma2(vb1, wb.y, aB[2*j+1]);
                }
            }
#pragma unroll
            for (int j = 0; j < 8; ++j) {
                u64 bp = reinterpret_cast<const u64*>(cbc)[c0/2 + j];
                sA = fma2(aA[j], aA[j], sA);  eA = fma2(aA[j], bp, eA);
                sB = fma2(aB[j], aB[j], sB);  eB = fma2(aB[j], bp, eB);
                P[(c0/2 + j) * 128] = aA[j];
                Q[(c0/2 + j) * 128] = aB[j];
            }
        }
        ss1A = hsum2(sA); d1cA = hsum2(eA);
        ss1B = hsum2(sB); d1cB = hsum2(eB);
    }

    // ======== branch 2: raw2 = logmap0(x2) @ Wc2 -> regs (rowA), R (rowB) ===
    float ss2A, ss2B, d2cA, d2cB, d12A, d12B;
    u64 r2A[32];
    {
        u64 uA[16], uB[16];
        load_log32p(gx2, rA, uA);
        load_log32p(gx2, rB, uB);
        u64 sA = 0, sB = 0, eA = 0, eB = 0, tA = 0, tB = 0;
#pragma unroll
        for (int c0 = 0; c0 < 64; c0 += 8) {
            u64 aA[4], aB[4];
#pragma unroll
            for (int j = 0; j < 4; ++j) { aA[j] = 0; aB[j] = 0; }
#pragma unroll
            for (int k2 = 0; k2 < 16; ++k2) {
                float lo, hi;
                upk2(uA[k2], lo, hi); const u64 va0 = pk2(lo, lo), va1 = pk2(hi, hi);
                upk2(uB[k2], lo, hi); const u64 vb0 = pk2(lo, lo), vb1 = pk2(hi, hi);
                const ulonglong2* w0 = reinterpret_cast<const ulonglong2*>(cWc2 + (2*k2)*64 + c0);
                const ulonglong2* w1 = reinterpret_cast<const ulonglong2*>(cWc2 + (2*k2+1)*64 + c0);
#pragma unroll
                for (int j = 0; j < 2; ++j) {
                    ulonglong2 wa = w0[j], wb = w1[j];
                    aA[2*j]   = fma2(va0, wa.x, aA[2*j]);   aA[2*j+1] = fma2(va0, wa.y, aA[2*j+1]);
                    aA[2*j]   = fma2(va1, wb.x, aA[2*j]);   aA[2*j+1] = fma2(va1, wb.y, aA[2*j+1]);
                    aB[2*j]   = fma2(vb0, wa.x, aB[2*j]);   aB[2*j+1] = fma2(vb0, wa.y, aB[2*j+1]);
                    aB[2*j]   = fma2(vb1, wb.x, aB[2*j]);   aB[2*j+1] = fma2(vb1, wb.y, aB[2*j+1]);
                }
            }
#pragma unroll
            for (int j = 0; j < 4; ++j) {
                int s = c0/2 + j;
                u64 bp = reinterpret_cast<const u64*>(cbc)[s];
                sA = fma2(aA[j], aA[j], sA);  eA = fma2(aA[j], bp, eA);
                sB = fma2(aB[j], aB[j], sB);  eB = fma2(aB[j], bp, eB);
                tA = fma2(aA[j], P[s * 128], tA);      // raw1A . raw2A
                tB = fma2(aB[j], Q[s * 128], tB);      // raw1B . raw2B
                r2A[s] = aA[j];
                R[s * 128] = aB[j];
            }
        }
        ss2A = hsum2(sA); d2cA = hsum2(eA); d12A = hsum2(tA);
        ss2B = hsum2(sB); d2cB = hsum2(eB); d12B = hsum2(tB);
    }

    // ======== concat scalar chains + combines ========
    float faA, fbA, fcA, faB, fbB, fcB;
    concat_coefs(ss1A, ss2A, d12A, d1cA, d2cA, bc2, faA, fbA, fcA);
    concat_coefs(ss1B, ss2B, d12B, d1cB, d2cB, bc2, faB, fbB, fcB);

    u64 vA[32];
    {
        const u64 fa2 = pk2(faA, faA), fb2 = pk2(fbA, fbA), fc2 = pk2(fcA, fcA);
        const u64 ga2 = pk2(faB, faB), gb2 = pk2(fbB, fbB), gc2 = pk2(fcB, fcB);
#pragma unroll
        for (int j = 0; j < 32; ++j) {
            u64 bp = reinterpret_cast<const u64*>(cbc)[j];
            vA[j] = fma2(fa2, P[j * 128], fma2(fb2, r2A[j], mul2(fc2, bp)));
            Q[j * 128] = fma2(ga2, Q[j * 128], fma2(gb2, R[j * 128], mul2(gc2, bp)));
        }
    }

    // ======== layer 0: raw3 = v @ W0 -> regs (rowA), P (rowB) ========
    float ss3A, ss3B, d3A, d3B;
    u64 r3A[32];
    {
        u64 sA = 0, sB = 0, eA = 0, eB = 0;
#pragma unroll
        for (int c0 = 0; c0 < 64; c0 += 8) {
            u64 aA[4], aB[4];
#pragma unroll
            for (int j = 0; j < 4; ++j) { aA[j] = 0; aB[j] = 0; }
#pragma unroll
            for (int k2 = 0; k2 < 32; ++k2) {
                float lo, hi;
                upk2(vA[k2], lo, hi);        const u64 va0 = pk2(lo, lo), va1 = pk2(hi, hi);
                upk2(Q[k2 * 128], lo, hi);   const u64 vb0 = pk2(lo, lo), vb1 = pk2(hi, hi);
                const ulonglong2* w0 = reinterpret_cast<const ulonglong2*>(cW0 + (2*k2)*64 + c0);
                const ulonglong2* w1 = reinterpret_cast<const ulonglong2*>(cW0 + (2*k2+1)*64 + c0);
#pragma unroll
                for (int j = 0; j < 2; ++j) {
                    ulonglong2 wa = w0[j], wb = w1[j];
                    aA[2*j]   = fma2(va0, wa.x, aA[2*j]);   aA[2*j+1] = fma2(va0, wa.y, aA[2*j+1]);
                    aA[2*j]   = fma2(va1, wb.x, aA[2*j]);   aA[2*j+1] = fma2(va1, wb.y, aA[2*j+1]);
                    aB[2*j]   = fma2(vb0, wa.x, aB[2*j]);   aB[2*j+1] = fma2(vb0, wa.y, aB[2*j+1]);
                    aB[2*j]   = fma2(vb1, wb.x, aB[2*j]);   aB[2*j+1] = fma2(vb1, wb.y, aB[2*j+1]);
                }
            }
#pragma unroll
            for (int j = 0; j < 4; ++j) {
                int s = c0/2 + j;
                u64 bp = reinterpret_cast<const u64*>(cb0)[s];
                sA = fma2(aA[j], aA[j], sA);  eA = fma2(aA[j], bp, eA);
                sB = fma2(aB[j], aB[j], sB);  eB = fma2(aB[j], bp, eB);
                r3A[s] = aA[j];
                P[s * 128] = aB[j];
            }
        }
        ss3A = hsum2(sA); d3A = hsum2(eA);
        ss3B = hsum2(sB); d3B = hsum2(eB);
    }

    // layer-0 scalar chains; combine into layer-1 inputs
    float fgA, fdA, fgB, fdB;
    layer_coefs(ss3A, d3A, b0sq, fgA, fdA);
    layer_coefs(ss3B, d3B, b0sq, fgB, fdB);
    {
        const u64 g2 = pk2(fgA, fgA), d2 = pk2(fdA, fdA);
        const u64 h2 = pk2(fgB, fgB), e2 = pk2(fdB, fdB);
#pragma unroll
        for (int j = 0; j < 32; ++j) {
            u64 bp = reinterpret_cast<const u64*>(cb0)[j];
            vA[j]      = fma2(g2, r3A[j],    mul2(d2, bp));
            P[j * 128] = fma2(h2, P[j * 128], mul2(e2, bp));
        }
    }

    // ======== layer 1: raw4 = v @ W1 -> regs (rowA), R (rowB) ========
    float ss4A, ss4B, d4A, d4B;
    u64 r4A[16];
    {
        u64 sA = 0, sB = 0, eA = 0, eB = 0;
#pragma unroll
        for (int c0 = 0; c0 < 32; c0 += 8) {
            u64 aA[4], aB[4];
#pragma unroll
            for (int j = 0; j < 4; ++j) { aA[j] = 0; aB[j] = 0; }
#pragma unroll
            for (int k2 = 0; k2 < 32; ++k2) {
                float lo, hi;
                upk2(vA[k2], lo, hi);        const u64 va0 = pk2(lo, lo), va1 = pk2(hi, hi);
                upk2(P[k2 * 128], lo, hi);   const u64 vb0 = pk2(lo, lo), vb1 = pk2(hi, hi);
                const ulonglong2* w0 = reinterpret_cast<const ulonglong2*>(cW1 + (2*k2)*32 + c0);
                const ulonglong2* w1 = reinterpret_cast<const ulonglong2*>(cW1 + (2*k2+1)*32 + c0);
#pragma unroll
                for (int j = 0; j < 2; ++j) {
                    ulonglong2 wa = w0[j], wb = w1[j];
                    aA[2*j]   = fma2(va0, wa.x, aA[2*j]);   aA[2*j+1] = fma2(va0, wa.y, aA[2*j+1]);
                    aA[2*j]   = fma2(va1, wb.x, aA[2*j]);   aA[2*j+1] = fma2(va1, wb.y, aA[2*j+1]);
                    aB[2*j]   = fma2(vb0, wa.x, aB[2*j]);   aB[2*j+1] = fma2(vb0, wa.y, aB[2*j+1]);
                    aB[2*j]   = fma2(vb1, wb.x, aB[2*j]);   aB[2*j+1] = fma2(vb1, wb.y, aB[2*j+1]);
                }
            }
#pragma unroll
            for (int j = 0; j < 4; ++j) {
                int s = c0/2 + j;
                u64 bp = reinterpret_cast<const u64*>(cb1)[s];
                sA = fma2(aA[j], aA[j], sA);  eA = fma2(aA[j], bp, eA);
                sB = fma2(aB[j], aB[j], sB);  eB = fma2(aB[j], bp, eB);
                r4A[s] = aA[j];
                R[s * 128] = aB[j];
            }
        }
        ss4A = hsum2(sA); d4A = hsum2(eA);
        ss4B = hsum2(sB); d4B = hsum2(eB);
    }

    // ======== final scalar chains + stores ========
    float paA, pbA, paB, pbB;
    out_coefs(ss4A, d4A, b1sq, paA, pbA);
    out_coefs(ss4B, d4B, b1sq, paB, pbB);

    float4* opA = reinterpret_cast<float4*>(gout + (size_t)rA * 32);
    float4* opB = reinterpret_cast<float4*>(gout + (size_t)rB * 32);
#pragma unroll
    for (int q = 0; q < 8; ++q) {
        float a0, a1, a2, a3, c0, c1, c2, c3;
        upk2(reinterpret_cast<const u64*>(cb1)[2*q],   c0, c1);
        upk2(reinterpret_cast<const u64*>(cb1)[2*q+1], c2, c3);
        upk2(r4A[2*q], a0, a1); upk2(r4A[2*q+1], a2, a3);
        opA[q] = make_float4(fmaf(paA, a0, pbA * c0), fmaf(paA, a1, pbA * c1),
                             fmaf(paA, a2, pbA * c2), fmaf(paA, a3, pbA * c3));
        upk2(R[(2*q) * 128], a0, a1); upk2(R[(2*q+1) * 128], a2, a3);
        opB[q] = make_float4(fmaf(paB, a0, pbB * c0), fmaf(paB, a1, pbB * c1),
                             fmaf(paB, a2, pbB * c2), fmaf(paB, a3, pbB * c3));
    }
}

// ---------------------------------------------------------------------------
// launch
// ---------------------------------------------------------------------------
extern "C" void kernel_launch(void* const* d_in, const int* in_sizes, int n_in,
                              void* d_out, int out_size)
{
    const float* x1 = (const float*)d_in[0];
    const float* x2 = (const float*)d_in[1];

    cudaMemcpyToSymbolAsync(cWc1, d_in[2], 32 * 64 * sizeof(float), 0, cudaMemcpyDeviceToDevice);
    cudaMemcpyToSymbolAsync(cWc2, d_in[3], 32 * 64 * sizeof(float), 0, cudaMemcpyDeviceToDevice);
    cudaMemcpyToSymbolAsync(cbc,  d_in[4], 64 * sizeof(float),      0, cudaMemcpyDeviceToDevice);
    cudaMemcpyToSymbolAsync(cW0,  d_in[5], 64 * 64 * sizeof(float), 0, cudaMemcpyDeviceToDevice);
    cudaMemcpyToSymbolAsync(cb0,  d_in[6], 64 * sizeof(float),      0, cudaMemcpyDeviceToDevice);
    cudaMemcpyToSymbolAsync(cW1,  d_in[7], 64 * 32 * sizeof(float), 0, cudaMemcpyDeviceToDevice);
    cudaMemcpyToSymbolAsync(cb1,  d_in[8], 32 * sizeof(float),      0, cudaMemcpyDeviceToDevice);

    // 96 u64-slots * 128 threads * 8B = 98304 bytes (2 CTAs/SM at 228KB)
    const int smem_bytes = 96 * 128 * 8;
    cudaFuncSetAttribute(poincare_mlp_kernel,
                         cudaFuncAttributeMaxDynamicSharedMemorySize, smem_bytes);

    float* out = (float*)d_out;
    const int N = in_sizes[0] / 32;
    const int blocks = (N + 255) / 256;
    poincare_mlp_kernel<<<blocks, 128, smem_bytes>>>(x1, x2, out, N);
}